// round 14
// baseline (speedup 1.0000x reference)
#include <cuda_runtime.h>
#include <cstdint>

#define N_MAX 100000
#define E_CONST 640000
#define FIN 128
#define F1 128
#define F2 64

// ---------------- device-resident scratch ----------------
// RULE: referenced ONLY inside device code (host-taken addresses of __device__
// symbols resolve to the ATS host shadow on GB300 -> 3ms C2C penalty).
// g_cnt invariant: zero at every kernel_launch entry (load-time zero-init;
// k_scan_all resets it to zero after consuming it each call).
__device__ __align__(128) float g_dinv[N_MAX];
__device__ __align__(128) float g_h1[(size_t)N_MAX * F1];
__device__ __align__(128) float g_y1[(size_t)N_MAX * F1];
__device__ __align__(128) float g_h2[(size_t)N_MAX * F2];
__device__ int g_cnt[N_MAX];
__device__ int g_rowptr[N_MAX + 1];
__device__ int g_woff[N_MAX];
__device__ int g_csrc[E_CONST];

// ---------------- degree count (precondition: g_cnt == 0) ----------------
__global__ void k_count(const int* __restrict__ edge, int e) {
    int i = blockIdx.x * blockDim.x + threadIdx.x;
    if (i < e) atomicAdd(&g_cnt[edge[e + i]], 1);  // dst
}

// ---------------- fused scan: rowptr + woff + dinv + cnt-reset, ONE block ------
__global__ void __launch_bounds__(1024) k_scan_all(int n) {
    __shared__ int sm[1024];
    const int t = threadIdx.x;
    const int chunk = (n + 1023) >> 10;
    const int beg = t * chunk;
    const int end = (beg + chunk < n) ? beg + chunk : n;

    int sum = 0;
    for (int i = beg; i < end; i++) sum += g_cnt[i];
    sm[t] = sum;
    __syncthreads();
    #pragma unroll
    for (int off = 1; off < 1024; off <<= 1) {
        int x = sm[t];
        if (t >= off) x += sm[t - off];
        __syncthreads();
        sm[t] = x;
        __syncthreads();
    }
    int run = (t > 0) ? sm[t - 1] : 0;  // exclusive prefix of this chunk
    for (int i = beg; i < end; i++) {
        int c = g_cnt[i];
        g_cnt[i] = 0;                    // restore invariant for next call
        g_woff[i] = run;
        run += c;
        g_rowptr[i + 1] = run;
        g_dinv[i] = rsqrtf(1.0f + (float)c);
    }
    if (t == 0) g_rowptr[0] = 0;
}

__global__ void k_fill(const int* __restrict__ edge, int e) {
    int i = blockIdx.x * blockDim.x + threadIdx.x;
    if (i < e) {
        int d = edge[e + i];
        int pos = atomicAdd(&g_woff[d], 1);
        g_csrc[pos] = edge[i];
    }
}

// ---------------- tiled GEMM body ----------------
template <int FOUT>
__device__ __forceinline__ void gemm_body(const float* __restrict__ X,
                                          const float* __restrict__ W,
                                          float* __restrict__ h, int n) {
    __shared__ float Xs[32 * FIN];
    __shared__ float Ws[FIN * 64];
    const int tid = threadIdx.x;
    const int row0 = blockIdx.x * 32;
    const int colbase = blockIdx.y * 64;

    for (int i = tid; i < 32 * FIN / 4; i += 256) {
        int r = i >> 5;
        int c4 = i & 31;
        int gr = row0 + r;
        float4 v = make_float4(0.f, 0.f, 0.f, 0.f);
        if (gr < n) v = *(const float4*)(X + (size_t)gr * FIN + c4 * 4);
        *(float4*)(Xs + r * FIN + c4 * 4) = v;
    }
    for (int i = tid; i < FIN * 64 / 4; i += 256) {
        int k = i >> 4;
        int c4 = i & 15;
        *(float4*)(Ws + k * 64 + c4 * 4) =
            *(const float4*)(W + (size_t)k * FOUT + colbase + c4 * 4);
    }
    __syncthreads();

    const int tx = tid & 31;
    const int ty = tid >> 5;

    float acc[4][2];
    #pragma unroll
    for (int r = 0; r < 4; r++) { acc[r][0] = 0.f; acc[r][1] = 0.f; }

    for (int k0 = 0; k0 < FIN; k0 += 4) {
        float4 xv[4];
        #pragma unroll
        for (int r = 0; r < 4; r++)
            xv[r] = *(const float4*)(Xs + (ty * 4 + r) * FIN + k0);
        #pragma unroll
        for (int kk = 0; kk < 4; kk++) {
            float w0 = Ws[(k0 + kk) * 64 + tx];
            float w1 = Ws[(k0 + kk) * 64 + tx + 32];
            #pragma unroll
            for (int r = 0; r < 4; r++) {
                float xe = (kk == 0) ? xv[r].x : (kk == 1) ? xv[r].y
                         : (kk == 2) ? xv[r].z : xv[r].w;
                acc[r][0] = fmaf(xe, w0, acc[r][0]);
                acc[r][1] = fmaf(xe, w1, acc[r][1]);
            }
        }
    }

    #pragma unroll
    for (int r = 0; r < 4; r++) {
        int gr = row0 + ty * 4 + r;
        if (gr < n) {
            h[(size_t)gr * FOUT + colbase + tx]      = acc[r][0];
            h[(size_t)gr * FOUT + colbase + tx + 32] = acc[r][1];
        }
    }
}

__global__ void __launch_bounds__(256) k_gemm1(const float* __restrict__ x,
                                               const float* __restrict__ W1, int n) {
    gemm_body<F1>(x, W1, g_h1, n);
}
__global__ void __launch_bounds__(256) k_gemm2(const float* __restrict__ W2, int n) {
    gemm_body<F2>(g_y1, W2, g_h2, n);
}

// ---------------- fused CSR aggregation ----------------
__global__ void k_agg_relu(const float* __restrict__ b, int n) {
    int node = (blockIdx.x * blockDim.x + threadIdx.x) >> 5;
    int lane = threadIdx.x & 31;
    if (node >= n) return;
    float dv = g_dinv[node];

    float4 acc = *(const float4*)(g_h1 + (size_t)node * F1 + lane * 4);
    acc.x *= dv; acc.y *= dv; acc.z *= dv; acc.w *= dv;

    int beg = g_rowptr[node], end = g_rowptr[node + 1];
    int i = beg;
    for (; i + 4 <= end; i += 4) {
        int s0 = g_csrc[i], s1 = g_csrc[i + 1], s2 = g_csrc[i + 2], s3 = g_csrc[i + 3];
        float w0 = g_dinv[s0], w1 = g_dinv[s1], w2 = g_dinv[s2], w3 = g_dinv[s3];
        float4 v0 = *(const float4*)(g_h1 + (size_t)s0 * F1 + lane * 4);
        float4 v1 = *(const float4*)(g_h1 + (size_t)s1 * F1 + lane * 4);
        float4 v2 = *(const float4*)(g_h1 + (size_t)s2 * F1 + lane * 4);
        float4 v3 = *(const float4*)(g_h1 + (size_t)s3 * F1 + lane * 4);
        acc.x = fmaf(w0, v0.x, fmaf(w1, v1.x, fmaf(w2, v2.x, fmaf(w3, v3.x, acc.x))));
        acc.y = fmaf(w0, v0.y, fmaf(w1, v1.y, fmaf(w2, v2.y, fmaf(w3, v3.y, acc.y))));
        acc.z = fmaf(w0, v0.z, fmaf(w1, v1.z, fmaf(w2, v2.z, fmaf(w3, v3.z, acc.z))));
        acc.w = fmaf(w0, v0.w, fmaf(w1, v1.w, fmaf(w2, v2.w, fmaf(w3, v3.w, acc.w))));
    }
    for (; i < end; i++) {
        int s = g_csrc[i];
        float w = g_dinv[s];
        float4 v = *(const float4*)(g_h1 + (size_t)s * F1 + lane * 4);
        acc.x = fmaf(w, v.x, acc.x);
        acc.y = fmaf(w, v.y, acc.y);
        acc.z = fmaf(w, v.z, acc.z);
        acc.w = fmaf(w, v.w, acc.w);
    }

    float4 bb = *(const float4*)(b + lane * 4);
    float4 o;
    o.x = fmaxf(fmaf(acc.x, dv, bb.x), 0.f);
    o.y = fmaxf(fmaf(acc.y, dv, bb.y), 0.f);
    o.z = fmaxf(fmaf(acc.z, dv, bb.z), 0.f);
    o.w = fmaxf(fmaf(acc.w, dv, bb.w), 0.f);
    *(float4*)(g_y1 + (size_t)node * F1 + lane * 4) = o;
}

__global__ void k_agg_lsm(const float* __restrict__ b, float* __restrict__ out, int n) {
    int node = (blockIdx.x * blockDim.x + threadIdx.x) >> 5;
    int lane = threadIdx.x & 31;
    if (node >= n) return;
    float dv = g_dinv[node];

    float2 acc = *(const float2*)(g_h2 + (size_t)node * F2 + lane * 2);
    acc.x *= dv; acc.y *= dv;

    int beg = g_rowptr[node], end = g_rowptr[node + 1];
    int i = beg;
    for (; i + 4 <= end; i += 4) {
        int s0 = g_csrc[i], s1 = g_csrc[i + 1], s2 = g_csrc[i + 2], s3 = g_csrc[i + 3];
        float w0 = g_dinv[s0], w1 = g_dinv[s1], w2 = g_dinv[s2], w3 = g_dinv[s3];
        float2 v0 = *(const float2*)(g_h2 + (size_t)s0 * F2 + lane * 2);
        float2 v1 = *(const float2*)(g_h2 + (size_t)s1 * F2 + lane * 2);
        float2 v2 = *(const float2*)(g_h2 + (size_t)s2 * F2 + lane * 2);
        float2 v3 = *(const float2*)(g_h2 + (size_t)s3 * F2 + lane * 2);
        acc.x = fmaf(w0, v0.x, fmaf(w1, v1.x, fmaf(w2, v2.x, fmaf(w3, v3.x, acc.x))));
        acc.y = fmaf(w0, v0.y, fmaf(w1, v1.y, fmaf(w2, v2.y, fmaf(w3, v3.y, acc.y))));
    }
    for (; i < end; i++) {
        int s = g_csrc[i];
        float w = g_dinv[s];
        float2 v = *(const float2*)(g_h2 + (size_t)s * F2 + lane * 2);
        acc.x = fmaf(w, v.x, acc.x);
        acc.y = fmaf(w, v.y, acc.y);
    }

    float2 bb = *(const float2*)(b + lane * 2);
    float v0 = fmaf(acc.x, dv, bb.x);
    float v1 = fmaf(acc.y, dv, bb.y);
    float m = fmaxf(v0, v1);
    #pragma unroll
    for (int o = 16; o; o >>= 1) m = fmaxf(m, __shfl_xor_sync(0xffffffffu, m, o));
    float s = expf(v0 - m) + expf(v1 - m);
    #pragma unroll
    for (int o = 16; o; o >>= 1) s += __shfl_xor_sync(0xffffffffu, s, o);
    float lse = m + logf(s);
    float2 o2 = make_float2(v0 - lse, v1 - lse);
    *(float2*)(out + (size_t)node * F2 + lane * 2) = o2;
}

// ---------------- launch ----------------
extern "C" void kernel_launch(void* const* d_in, const int* in_sizes, int n_in,
                              void* d_out, int out_size) {
    const float* x  = (const float*)d_in[0];
    const int* edge = (const int*)d_in[1];   // int32 [2, E]
    const float* W1 = (const float*)d_in[2];
    const float* b1 = (const float*)d_in[3];
    const float* W2 = (const float*)d_in[4];
    const float* b2 = (const float*)d_in[5];
    float* out = (float*)d_out;

    const int n = in_sizes[0] / FIN;  // 100000
    const int e = E_CONST;            // 640000
    const int T = 256;
    const long long aggth = (long long)n * 32;
    const int aggblk = (int)((aggth + T - 1) / T);
    const dim3 grid1((n + 31) / 32, F1 / 64);
    const dim3 grid2((n + 31) / 32, F2 / 64);

    // side stream + events (created once, on the first/eager call)
    static cudaStream_t s2 = nullptr;
    static cudaEvent_t ev0 = nullptr, ev1 = nullptr;
    if (!s2) {
        cudaStreamCreateWithFlags(&s2, cudaStreamNonBlocking);
        cudaEventCreateWithFlags(&ev0, cudaEventDisableTiming);
        cudaEventCreateWithFlags(&ev1, cudaEventDisableTiming);
    }

    // fork: GEMM1 (only needs x, W1) overlaps the CSR chain
    cudaEventRecord(ev0, 0);
    cudaStreamWaitEvent(s2, ev0, 0);
    k_gemm1<<<grid1, T, 0, s2>>>(x, W1, n);
    cudaEventRecord(ev1, s2);

    // CSR chain on default stream
    k_count<<<(e + T - 1) / T, T>>>(edge, e);
    k_scan_all<<<1, 1024>>>(n);
    k_fill<<<(e + T - 1) / T, T>>>(edge, e);

    // join: aggregation needs h1 + CSR
    cudaStreamWaitEvent(0, ev1, 0);
    k_agg_relu<<<aggblk, T>>>(b1, n);

    k_gemm2<<<grid2, T>>>(W2, n);
    k_agg_lsm<<<aggblk, T>>>(b2, out, n);
}